// round 1
// baseline (speedup 1.0000x reference)
#include <cuda_runtime.h>
#include <cuda_fp16.h>

#define BSZ   256
#define MM    128
#define NN    1024
#define ITERS 100
#define ALPHA 0.1f

// Scratch (static __device__ globals are the sanctioned scratch mechanism).
__device__ __half g_Ah[(size_t)BSZ * MM * NN];   // A in fp16, 67 MB (L2-resident)
__device__ float  g_C[(size_t)BSZ * MM * MM];    // AAT, then its inverse, 16 MB

// ---------------------------------------------------------------------------
// Kernel 1: convert A fp32 -> fp16
// ---------------------------------------------------------------------------
__global__ void k_convert(const float* __restrict__ A) {
    size_t i = ((size_t)blockIdx.x * blockDim.x + threadIdx.x) * 4;
    float4 v = *(const float4*)(A + i);
    __half2* dst = (__half2*)(g_Ah + i);
    dst[0] = __floats2half2_rn(v.x, v.y);
    dst[1] = __floats2half2_rn(v.z, v.w);
}

// ---------------------------------------------------------------------------
// Kernel 2: AAT[b] = A_h[b] @ A_h[b]^T  (computed from the fp16-rounded A so
// the projection is exact for the perturbed operator). One CTA per batch,
// 16x16 threads, each computing an 8x8 block (rows i = ty+16*ii, cols j = tx+16*jj).
// ---------------------------------------------------------------------------
__global__ void __launch_bounds__(256) k_aat() {
    __shared__ float sA[128 * 33];   // 128 rows x 32 k-cols, pad 33 (conflict-free)
    int b = blockIdx.x, t = threadIdx.x;
    const __half* Ab = g_Ah + (size_t)b * MM * NN;
    int ty = t >> 4, tx = t & 15;

    float acc[8][8];
#pragma unroll
    for (int ii = 0; ii < 8; ii++)
#pragma unroll
        for (int jj = 0; jj < 8; jj++) acc[ii][jj] = 0.0f;

    for (int k0 = 0; k0 < NN; k0 += 32) {
        // load 128x32 tile (each thread: one half-row of 16 halves)
        int tr = t >> 1, tc0 = (t & 1) * 16;
        const __half2* src = (const __half2*)(Ab + (size_t)tr * NN + k0 + tc0);
        float* dst = &sA[tr * 33 + tc0];
#pragma unroll
        for (int q = 0; q < 8; q++) {
            float2 f = __half22float2(src[q]);
            dst[2 * q] = f.x; dst[2 * q + 1] = f.y;
        }
        __syncthreads();

#pragma unroll 4
        for (int kk = 0; kk < 32; kk++) {
            float a[8], c[8];
#pragma unroll
            for (int ii = 0; ii < 8; ii++) a[ii] = sA[(ty + 16 * ii) * 33 + kk];
#pragma unroll
            for (int jj = 0; jj < 8; jj++) c[jj] = sA[(tx + 16 * jj) * 33 + kk];
#pragma unroll
            for (int ii = 0; ii < 8; ii++)
#pragma unroll
                for (int jj = 0; jj < 8; jj++)
                    acc[ii][jj] += a[ii] * c[jj];
        }
        __syncthreads();
    }

    float* Cb = g_C + (size_t)b * MM * MM;
#pragma unroll
    for (int ii = 0; ii < 8; ii++)
#pragma unroll
        for (int jj = 0; jj < 8; jj++)
            Cb[(ty + 16 * ii) * MM + (tx + 16 * jj)] = acc[ii][jj];
}

// ---------------------------------------------------------------------------
// Kernel 3: in-place Gauss-Jordan inverse of AAT[b] (SPD, well-conditioned;
// no pivoting needed). One CTA per batch, matrix in smem.
// ---------------------------------------------------------------------------
__global__ void __launch_bounds__(256) k_inv() {
    extern __shared__ float sm[];
    float* sM = sm;            // 16384
    float* sf = sm + 16384;    // 128
    float* sp = sm + 16512;    // 1
    int b = blockIdx.x, t = threadIdx.x;
    float* Cb = g_C + (size_t)b * MM * MM;

    for (int i = t; i < 4096; i += 256) ((float4*)sM)[i] = ((const float4*)Cb)[i];
    __syncthreads();

    for (int k = 0; k < 128; k++) {
        if (t == 0) sp[0] = 1.0f / sM[k * 128 + k];
        __syncthreads();
        float ipiv = sp[0];
        if (t < 128) {
            float v = sM[k * 128 + t];
            sM[k * 128 + t] = (t == k) ? ipiv : v * ipiv;     // scale row k (pivot slot = 1/p)
            sf[t] = (t == k) ? 0.0f : sM[t * 128 + k];        // stash multipliers
        }
        __syncthreads();
        int j = t & 127, i0 = (t >> 7) * 64;
        float mk = sM[k * 128 + j];
#pragma unroll 4
        for (int ii = 0; ii < 64; ii++) {
            int i = i0 + ii;
            if (i == k) continue;
            float fi = sf[i];
            float v = sM[i * 128 + j];
            sM[i * 128 + j] = (j == k) ? (-fi * mk) : (v - fi * mk);
        }
        __syncthreads();
    }

    for (int i = t; i < 4096; i += 256) ((float4*)Cb)[i] = ((const float4*)sM)[i];
}

// ---------------------------------------------------------------------------
// Kernel 4: 100 DR iterations, one CTA per batch (256 CTAs, single wave).
// State z, x_half, thresholds live in registers (thread t owns elements 4t..4t+3
// == cols 128w+4lane, so elementwise ownership matches pass-2 ownership).
// AAT^{-1} cached in smem. Per iteration: 3 syncthreads.
//   z' = x_half - corr,  x_new = y - corr,  corr = A^T C (A y - b), y = 2 x_half - z
// ---------------------------------------------------------------------------
__global__ void __launch_bounds__(256) k_iter(const float* __restrict__ bvec,
                                              const float* __restrict__ D1,
                                              const float* __restrict__ D2,
                                              float* __restrict__ out) {
    extern __shared__ float sm[];
    float* sC = sm;               // 16384
    float* sy = sm + 16384;       // 1024
    float* sb = sy + 1024;        // 128
    float* sr = sb + 128;         // 128
    float* su = sr + 128;         // 128

    int b = blockIdx.x, t = threadIdx.x;
    int w = t >> 5, lane = t & 31;
    const __half* Ab = g_Ah + (size_t)b * MM * NN;
    const float*  Cb = g_C  + (size_t)b * MM * MM;

    for (int i = t; i < 4096; i += 256) ((float4*)sC)[i] = ((const float4*)Cb)[i];
    if (t < 128) sb[t] = bvec[(size_t)b * MM + t];

    // per-thread element params (elements 4t..4t+3)
    float4 d1 = *(const float4*)(D1 + (size_t)b * NN + 4 * t);
    float4 d2 = *(const float4*)(D2 + (size_t)b * NN + 4 * t);
    float thr[4], dv[4], z[4], xnew[4];
    thr[0] = ALPHA * fabsf(d1.x); thr[1] = ALPHA * fabsf(d1.y);
    thr[2] = ALPHA * fabsf(d1.z); thr[3] = ALPHA * fabsf(d1.w);
    dv[0] = 1.0f / (1.0f + 2.0f * ALPHA * d2.x * d2.x);
    dv[1] = 1.0f / (1.0f + 2.0f * ALPHA * d2.y * d2.y);
    dv[2] = 1.0f / (1.0f + 2.0f * ALPHA * d2.z * d2.z);
    dv[3] = 1.0f / (1.0f + 2.0f * ALPHA * d2.w * d2.w);
#pragma unroll
    for (int i = 0; i < 4; i++) { z[i] = 0.0f; xnew[i] = 0.0f; }
    __syncthreads();

    for (int it = 0; it < ITERS; it++) {
        // --- elementwise: x_half = soft(z), y = 2*x_half - z ---
        float xh[4], yv[4];
#pragma unroll
        for (int i = 0; i < 4; i++) {
            float zi = z[i];
            float a = zi - thr[i], c = zi + thr[i];
            float v = (a > 0.0f) ? a * dv[i] : ((c < 0.0f) ? c * dv[i] : 0.0f);
            xh[i] = v;
            yv[i] = 2.0f * v - zi;
        }
        *(float4*)&sy[4 * t] = make_float4(yv[0], yv[1], yv[2], yv[3]);
        __syncthreads();                                      // sync 1: y ready

        // broadcast copy of y into registers: yr[k] = y[128k + 4*lane .. +3]
        float4 yr[8];
#pragma unroll
        for (int k = 0; k < 8; k++) yr[k] = *(float4*)&sy[128 * k + 4 * lane];

        // --- pass 1: r = A y - b. warp w handles rows 16w..16w+15 ---
#pragma unroll 2
        for (int rr = 0; rr < 16; rr++) {
            int row = w * 16 + rr;
            const uint2* ap = (const uint2*)(Ab + (size_t)row * NN);
            float acc = 0.0f;
#pragma unroll
            for (int k = 0; k < 8; k++) {
                union { uint2 u; __half2 h[2]; } cv;
                cv.u = ap[32 * k + lane];
                float2 f0 = __half22float2(cv.h[0]);
                float2 f1 = __half22float2(cv.h[1]);
                acc += f0.x * yr[k].x + f0.y * yr[k].y + f1.x * yr[k].z + f1.y * yr[k].w;
            }
#pragma unroll
            for (int off = 16; off > 0; off >>= 1)
                acc += __shfl_xor_sync(0xffffffffu, acc, off);
            if (lane == 0) sr[row] = acc - sb[row];
        }
        __syncthreads();                                      // sync 2: r ready

        // --- u = C r (2 threads per row, staggered float4 reads) ---
        {
            int i = t >> 1, h = t & 1, base = i & 15;
            float accu = 0.0f;
#pragma unroll
            for (int m = 0; m < 16; m++) {
                int j = 64 * h + 4 * ((base + m) & 15);
                float4 c4 = *(float4*)&sC[i * 128 + j];
                float4 r4 = *(float4*)&sr[j];
                accu += c4.x * r4.x + c4.y * r4.y + c4.z * r4.z + c4.w * r4.w;
            }
            accu += __shfl_xor_sync(0xffffffffu, accu, 1);
            if (h == 0) su[i] = accu;
        }
        __syncthreads();                                      // sync 3: u ready

        // --- pass 2: corr[c] = sum_r A[r][c] * u[r], cols c = 4t..4t+3 ---
        float corr[4] = {0.0f, 0.0f, 0.0f, 0.0f};
        const uint2* ap2 = (const uint2*)Ab + (32 * w + lane);
#pragma unroll 8
        for (int r = 0; r < 128; r++) {
            float ur = su[r];
            union { uint2 u; __half2 h[2]; } cv;
            cv.u = ap2[(size_t)r * 256];
            float2 f0 = __half22float2(cv.h[0]);
            float2 f1 = __half22float2(cv.h[1]);
            corr[0] += f0.x * ur; corr[1] += f0.y * ur;
            corr[2] += f1.x * ur; corr[3] += f1.y * ur;
        }

        // --- epilogue: x_new = y - corr, z' = x_half - corr ---
#pragma unroll
        for (int i = 0; i < 4; i++) {
            xnew[i] = yv[i] - corr[i];
            z[i]    = xh[i] - corr[i];
        }
        // No trailing sync needed: sy is only re-read after sync 1 of the next
        // iteration; sr/su are only re-written after the next iteration's syncs.
    }

    *(float4*)(out + (size_t)b * NN + 4 * t) =
        make_float4(xnew[0], xnew[1], xnew[2], xnew[3]);
}

// ---------------------------------------------------------------------------
extern "C" void kernel_launch(void* const* d_in, const int* in_sizes, int n_in,
                              void* d_out, int out_size) {
    const float* A  = (const float*)d_in[0];
    const float* bv = (const float*)d_in[1];
    const float* D1 = (const float*)d_in[2];
    const float* D2 = (const float*)d_in[3];
    float* out = (float*)d_out;

    cudaFuncSetAttribute(k_inv,  cudaFuncAttributeMaxDynamicSharedMemorySize, 66052);
    cudaFuncSetAttribute(k_iter, cudaFuncAttributeMaxDynamicSharedMemorySize, 71168);

    // total elements = 256*128*1024 = 33,554,432; 4 per thread, 256 per block
    k_convert<<<32768, 256>>>(A);
    k_aat<<<BSZ, 256>>>();
    k_inv<<<BSZ, 256, 66052>>>();
    k_iter<<<BSZ, 256, 71168>>>(bv, D1, D2, out);
}